// round 1
// baseline (speedup 1.0000x reference)
#include <cuda_runtime.h>

// ---------------------------------------------------------------------------
// Problem constants
// ---------------------------------------------------------------------------
namespace {
constexpr int NB = 32;       // batch
constexpr int NT = 64;       // decode steps
constexpr int NS = 128;      // source length
constexpr int EH = 512;      // encoder hidden
constexpr int DH = 512;      // decoder hidden
constexpr int NA = 256;      // attention dim
constexpr int NE = 256;      // embedding dim
constexpr int NV = 31999;    // vocab - 1 (FC output width)
constexpr int IND = NE + EH; // 768, GRU input dim
}

// ---------------------------------------------------------------------------
// Device scratch (no allocations allowed)
// ---------------------------------------------------------------------------
__device__ __align__(16) float g_enc_proj[NB * NS * NA]; // 4 MB
__device__ __align__(16) float g_h[NT * NB * DH];        // 4 MB, h_t for all steps
__device__ __align__(16) float g_ctx[NB * EH];           // per-step context

// ---------------------------------------------------------------------------
// f32x2 packed-FMA helpers (sm_10x)
// ---------------------------------------------------------------------------
__device__ __forceinline__ unsigned long long pack2(float lo, float hi) {
    unsigned long long r;
    asm("mov.b64 %0, {%1, %2};" : "=l"(r) : "f"(lo), "f"(hi));
    return r;
}
__device__ __forceinline__ void ffma2(unsigned long long& c, unsigned long long a,
                                      unsigned long long b) {
    asm("fma.rn.f32x2 %0, %1, %2, %0;" : "+l"(c) : "l"(a), "l"(b));
}
__device__ __forceinline__ void unpack2(unsigned long long v, float& lo, float& hi) {
    asm("mov.b64 {%0, %1}, %2;" : "=f"(lo), "=f"(hi) : "l"(v));
}

__device__ __forceinline__ float fast_tanh(float x) {
    // 1 - 2/(e^{2x}+1): monotone-safe at +-inf (no inf/inf), ~1e-6 rel err
    float e2 = __expf(2.0f * x);
    return 1.0f - 2.0f / (e2 + 1.0f);
}
__device__ __forceinline__ float fast_sigmoid(float x) {
    return 1.0f / (1.0f + __expf(-x));
}

// ---------------------------------------------------------------------------
// K0: enc_proj[b,s,:] = encoder_outputs[b,s,:] @ W_enc    (once)
// grid = NB*NS blocks, 256 threads (one thread per attention column)
// ---------------------------------------------------------------------------
__global__ void k_encproj(const float* __restrict__ enc,
                          const float* __restrict__ W_enc) {
    const int rs = blockIdx.x; // b*NS + s
    __shared__ float row[EH];
    for (int i = threadIdx.x; i < EH; i += 256) row[i] = enc[rs * EH + i];
    __syncthreads();
    const int a = threadIdx.x; // 0..255
    float acc = 0.f;
#pragma unroll 8
    for (int h = 0; h < EH; h++) acc += row[h] * W_enc[h * NA + a];
    g_enc_proj[rs * NA + a] = acc;
}

// ---------------------------------------------------------------------------
// K1: attention for step t. One block per batch element, 256 threads.
// dec = prev @ W_dec ; energy = tanh(enc_proj + dec) . v ; softmax ;
// context = aw @ encoder_outputs ; writes aw into d_out attn region.
// ---------------------------------------------------------------------------
__global__ void k_attn(int t,
                       const float* __restrict__ enc,
                       const float* __restrict__ dec_init,
                       const int* __restrict__ mask,
                       const float* __restrict__ W_dec,
                       const float* __restrict__ v,
                       float* __restrict__ attn_out) {
    const int b = blockIdx.x;
    const int tid = threadIdx.x;

    __shared__ float prev[DH];
    __shared__ float dec[NA];
    __shared__ float epart[2][NS];
    __shared__ float e[NS];
    __shared__ float red[NS];

    const float* pv = (t == 0) ? (dec_init + b * DH)
                               : (g_h + ((t - 1) * NB + b) * DH);
    prev[tid] = pv[tid];
    prev[tid + 256] = pv[tid + 256];
    __syncthreads();

    // dec[a] = sum_h prev[h] * W_dec[h,a]   (W_dec coalesced across a)
    {
        float acc = 0.f;
#pragma unroll 8
        for (int h = 0; h < DH; h++) acc += prev[h] * W_dec[h * NA + tid];
        dec[tid] = acc;
    }
    __syncthreads();

    // energy partials: threads 0..127 -> a in [0,128), 128..255 -> a in [128,256)
    {
        const int half = tid >> 7;
        const int s = tid & 127;
        const float* ep = g_enc_proj + (b * NS + s) * NA + half * 128;
        const float* dv = dec + half * 128;
        const float* vv = v + half * 128;
        float acc = 0.f;
#pragma unroll 4
        for (int a = 0; a < 128; a++) {
            float x = ep[a] + dv[a];
            acc += fast_tanh(x) * vv[a];
        }
        epart[half][s] = acc;
    }
    __syncthreads();

    if (tid < NS) {
        float en = epart[0][tid] + epart[1][tid];
        if (mask[b * NS + tid] == 0) en = -1e9f;
        e[tid] = en;
        red[tid] = en;
    }
    __syncthreads();
    // max reduce
    for (int off = 64; off > 0; off >>= 1) {
        if (tid < off) red[tid] = fmaxf(red[tid], red[tid + off]);
        __syncthreads();
    }
    const float mx = red[0];
    __syncthreads();
    if (tid < NS) {
        float ex = __expf(e[tid] - mx);
        e[tid] = ex;
        red[tid] = ex;
    }
    __syncthreads();
    // sum reduce
    for (int off = 64; off > 0; off >>= 1) {
        if (tid < off) red[tid] += red[tid + off];
        __syncthreads();
    }
    const float inv = 1.0f / red[0];
    __syncthreads();
    if (tid < NS) {
        float aw = e[tid] * inv;
        e[tid] = aw;
        attn_out[((size_t)(b * NT + t)) * NS + tid] = aw;
    }
    __syncthreads();

    // context[d] = sum_s aw[s] * enc[b,s,d]   (coalesced across d)
#pragma unroll
    for (int rep = 0; rep < 2; rep++) {
        const int d = tid + rep * 256;
        const float* eb = enc + (size_t)b * NS * EH + d;
        float acc = 0.f;
#pragma unroll 4
        for (int s = 0; s < NS; s++) acc += e[s] * eb[s * EH];
        g_ctx[b * EH + d] = acc;
    }
}

// ---------------------------------------------------------------------------
// K2: GRU gates + state update for step t.
// grid = NB*16 blocks (block = (b, chunk of 32 hidden idx)), 256 threads.
// Each warp handles 4 hidden indices; per index: 6 warp-reduced dot products
// (gx_r/gh_r/gx_z/gh_z/gx_n/gh_n), then lane0 combines and writes h_t.
// ---------------------------------------------------------------------------
__global__ void k_gru(int t,
                      const int* __restrict__ y,
                      const float* __restrict__ dec_init,
                      const float* __restrict__ embedding,
                      const float* __restrict__ W_ih,
                      const float* __restrict__ W_hh,
                      const float* __restrict__ b_ih,
                      const float* __restrict__ b_hh) {
    const int b = blockIdx.x >> 4;
    const int i0 = (blockIdx.x & 15) * 32;
    const int tid = threadIdx.x;
    const int lane = tid & 31;
    const int w = tid >> 5;

    __shared__ float x[IND];
    __shared__ float prev[DH];

    const float* pv = (t == 0) ? (dec_init + b * DH)
                               : (g_h + ((t - 1) * NB + b) * DH);
    const int tok = y[b * NT + t];
    for (int i = tid; i < NE; i += 256) x[i] = embedding[(size_t)tok * NE + i];
    for (int i = tid; i < EH; i += 256) x[NE + i] = g_ctx[b * EH + i];
    for (int i = tid; i < DH; i += 256) prev[i] = pv[i];
    __syncthreads();

#pragma unroll
    for (int ii = 0; ii < 4; ii++) {
        const int i = i0 + w * 4 + ii;
        float gx[3], gh[3];
#pragma unroll
        for (int g = 0; g < 3; g++) {
            const int row = g * DH + i;
            const float* wi = W_ih + (size_t)row * IND;
            const float* wh = W_hh + (size_t)row * DH;
            float ax = 0.f, ah = 0.f;
#pragma unroll
            for (int k = lane; k < IND; k += 32) ax += wi[k] * x[k];
#pragma unroll
            for (int k = lane; k < DH; k += 32) ah += wh[k] * prev[k];
#pragma unroll
            for (int off = 16; off > 0; off >>= 1) {
                ax += __shfl_down_sync(0xffffffffu, ax, off);
                ah += __shfl_down_sync(0xffffffffu, ah, off);
            }
            gx[g] = ax;
            gh[g] = ah;
        }
        if (lane == 0) {
            float xr = gx[0] + b_ih[i],        hr = gh[0] + b_hh[i];
            float xz = gx[1] + b_ih[DH + i],   hz = gh[1] + b_hh[DH + i];
            float xn = gx[2] + b_ih[2*DH + i], hn = gh[2] + b_hh[2*DH + i];
            float r = fast_sigmoid(xr + hr);
            float z = fast_sigmoid(xz + hz);
            float n = fast_tanh(xn + r * hn);
            float p = prev[i];
            g_h[((size_t)t * NB + b) * DH + i] = (1.0f - z) * n + z * p;
        }
    }
}

// ---------------------------------------------------------------------------
// K3: batched FC:  out[(b,t), n] = h_all[(t,b), :] @ W_fc + b_fc
// M=2048, N=31999, K=512. 128x128x8 tiles, 8x8 per thread, f32x2 packed FMA
// (packed over the M dimension; A tile stored transposed in smem).
// ---------------------------------------------------------------------------
constexpr int FBM = 128, FBN = 128, FBK = 8;

__global__ void __launch_bounds__(256) k_fc(const float* __restrict__ Wfc,
                                            const float* __restrict__ bfc,
                                            float* __restrict__ out) {
    __shared__ __align__(16) float As[FBK][FBM]; // [k][m] (transposed)
    __shared__ __align__(16) float Bs[FBK][FBN]; // [k][n]

    const int n0 = blockIdx.x * FBN;
    const int m0 = blockIdx.y * FBM;
    const int tid = threadIdx.x;
    const int tx = tid & 15;  // n quadrant lane
    const int ty = tid >> 4;  // m quadrant lane
    const int am = tid >> 1;           // 0..127
    const int ak4 = (tid & 1) * 4;     // 0 or 4
    const int bk = tid >> 5;           // 0..7
    const int bn = (tid & 31) * 4;     // 0..124

    unsigned long long c2[2][2][2][4]; // [hA][ip][hB][j], packed over m-pairs
#pragma unroll
    for (int a = 0; a < 2; a++)
#pragma unroll
        for (int p = 0; p < 2; p++)
#pragma unroll
            for (int h = 0; h < 2; h++)
#pragma unroll
                for (int j = 0; j < 4; j++) c2[a][p][h][j] = 0ull;

    for (int kt = 0; kt < DH; kt += FBK) {
        // A tile: g_h rows are 512 floats, 16B-aligned -> float4 load
        float4 a4 = *reinterpret_cast<const float4*>(
            &g_h[(size_t)(m0 + am) * DH + kt + ak4]);
        As[ak4 + 0][am] = a4.x;
        As[ak4 + 1][am] = a4.y;
        As[ak4 + 2][am] = a4.z;
        As[ak4 + 3][am] = a4.w;
        // B tile: W_fc rows are 31999 floats (odd) -> scalar guarded loads
#pragma unroll
        for (int q = 0; q < 4; q++) {
            int n = n0 + bn + q;
            Bs[bk][bn + q] = (n < NV) ? Wfc[(size_t)(kt + bk) * NV + n] : 0.f;
        }
        __syncthreads();

#pragma unroll
        for (int kk = 0; kk < FBK; kk++) {
            unsigned long long a2[2][2];
            float4 bv[2];
#pragma unroll
            for (int h = 0; h < 2; h++) {
                float4 av = *reinterpret_cast<const float4*>(&As[kk][h * 64 + ty * 4]);
                a2[h][0] = pack2(av.x, av.y);
                a2[h][1] = pack2(av.z, av.w);
                bv[h] = *reinterpret_cast<const float4*>(&Bs[kk][h * 64 + tx * 4]);
            }
#pragma unroll
            for (int hb = 0; hb < 2; hb++) {
                float bj[4] = {bv[hb].x, bv[hb].y, bv[hb].z, bv[hb].w};
#pragma unroll
                for (int j = 0; j < 4; j++) {
                    unsigned long long b2 = pack2(bj[j], bj[j]);
#pragma unroll
                    for (int ha = 0; ha < 2; ha++)
#pragma unroll
                        for (int ip = 0; ip < 2; ip++)
                            ffma2(c2[ha][ip][hb][j], a2[ha][ip], b2);
                }
            }
        }
        __syncthreads();
    }

    // epilogue: row m of h_all maps to (t = m>>5, b = m&31); out is [b][t][n]
#pragma unroll
    for (int ha = 0; ha < 2; ha++)
#pragma unroll
        for (int ip = 0; ip < 2; ip++) {
            const int m = m0 + ha * 64 + ty * 4 + ip * 2;
#pragma unroll
            for (int hb = 0; hb < 2; hb++)
#pragma unroll
                for (int j = 0; j < 4; j++) {
                    const int n = n0 + hb * 64 + tx * 4 + j;
                    if (n < NV) {
                        float lo, hi;
                        unpack2(c2[ha][ip][hb][j], lo, hi);
                        const float bias = bfc[n];
                        const int t1 = m >> 5, b1 = m & 31;
                        const int t2 = (m + 1) >> 5, b2i = (m + 1) & 31;
                        out[((size_t)(b1 * NT + t1)) * NV + n] = lo + bias;
                        out[((size_t)(b2i * NT + t2)) * NV + n] = hi + bias;
                    }
                }
        }
}

// ---------------------------------------------------------------------------
// Launch
// ---------------------------------------------------------------------------
extern "C" void kernel_launch(void* const* d_in, const int* in_sizes, int n_in,
                              void* d_out, int out_size) {
    const int* y = (const int*)d_in[0];         // (B,T) int32
    const float* enc = (const float*)d_in[1];   // (B,S,EH)
    const float* dec_init = (const float*)d_in[2]; // (1,B,DH)
    const int* mask = (const int*)d_in[3];      // (B,S) int32
    const float* emb = (const float*)d_in[4];   // (VOCAB,NE)
    const float* W_enc = (const float*)d_in[5]; // (EH,NA)
    const float* W_dec = (const float*)d_in[6]; // (DH,NA)
    const float* v = (const float*)d_in[7];     // (NA,)
    const float* W_ih = (const float*)d_in[8];  // (3DH, IND)
    const float* W_hh = (const float*)d_in[9];  // (3DH, DH)
    const float* b_ih = (const float*)d_in[10]; // (3DH,)
    const float* b_hh = (const float*)d_in[11]; // (3DH,)
    const float* W_fc = (const float*)d_in[12]; // (DH, NV)
    const float* b_fc = (const float*)d_in[13]; // (NV,)

    float* out = (float*)d_out;                          // (B,T,NV) first
    float* attn_out = out + (size_t)NB * NT * NV;        // then (B,T,S)

    k_encproj<<<NB * NS, 256>>>(enc, W_enc);
    for (int t = 0; t < NT; t++) {
        k_attn<<<NB, 256>>>(t, enc, dec_init, mask, W_dec, v, attn_out);
        k_gru<<<NB * 16, 256>>>(t, y, dec_init, emb, W_ih, W_hh, b_ih, b_hh);
    }
    dim3 gfc((NV + FBN - 1) / FBN, (NB * NT) / FBM); // 250 x 16
    k_fc<<<gfc, 256>>>(W_fc, b_fc, out);
}

// round 2
// speedup vs baseline: 1.1796x; 1.1796x over previous
#include <cuda_runtime.h>

// ---------------------------------------------------------------------------
// Problem constants
// ---------------------------------------------------------------------------
namespace {
constexpr int NB = 32;       // batch
constexpr int NT = 64;       // decode steps
constexpr int NS = 128;      // source length
constexpr int EH = 512;      // encoder hidden
constexpr int DH = 512;      // decoder hidden
constexpr int NA = 256;      // attention dim
constexpr int NE = 256;      // embedding dim
constexpr int NV = 31999;    // vocab - 1 (FC output width)
constexpr int IND = NE + EH; // 768, GRU input dim
}

// ---------------------------------------------------------------------------
// Device scratch (no allocations allowed)
// ---------------------------------------------------------------------------
__device__ __align__(16) float g_encT[NB * NA * NS];  // enc_proj transposed [b][a][s]
__device__ __align__(16) float g_h[NT * NB * DH];     // h_t for all steps
__device__ __align__(16) float g_ctx[NB * EH];        // per-step context

// ---------------------------------------------------------------------------
// math helpers
// ---------------------------------------------------------------------------
__device__ __forceinline__ unsigned long long pack2(float lo, float hi) {
    unsigned long long r;
    asm("mov.b64 %0, {%1, %2};" : "=l"(r) : "f"(lo), "f"(hi));
    return r;
}
__device__ __forceinline__ void ffma2(unsigned long long& c, unsigned long long a,
                                      unsigned long long b) {
    asm("fma.rn.f32x2 %0, %1, %2, %0;" : "+l"(c) : "l"(a), "l"(b));
}
__device__ __forceinline__ void unpack2(unsigned long long v, float& lo, float& hi) {
    asm("mov.b64 {%0, %1}, %2;" : "=f"(lo), "=f"(hi) : "l"(v));
}
__device__ __forceinline__ float tanh_hw(float x) {  // MUFU.TANH, ~5e-4 abs err
    float y;
    asm("tanh.approx.f32 %0, %1;" : "=f"(y) : "f"(x));
    return y;
}
__device__ __forceinline__ float fast_tanh(float x) {  // precise path (GRU)
    float e2 = __expf(2.0f * x);
    return 1.0f - 2.0f / (e2 + 1.0f);
}
__device__ __forceinline__ float fast_sigmoid(float x) {
    return 1.0f / (1.0f + __expf(-x));
}

// ---------------------------------------------------------------------------
// K0: enc_projT[b][a][s] = sum_h enc[b,s,h] * W_enc[h,a]   (once)
// grid = NB*NS blocks, 256 threads (thread = attention column a)
// ---------------------------------------------------------------------------
__global__ void k_encproj(const float* __restrict__ enc,
                          const float* __restrict__ W_enc) {
    const int rs = blockIdx.x;  // b*NS + s
    const int b = rs >> 7;
    const int s = rs & 127;
    __shared__ float row[EH];
    for (int i = threadIdx.x; i < EH; i += 256) row[i] = enc[rs * EH + i];
    __syncthreads();
    const int a = threadIdx.x;
    float acc0 = 0.f, acc1 = 0.f;
#pragma unroll 8
    for (int h = 0; h < EH; h += 2) {
        acc0 += row[h] * W_enc[h * NA + a];
        acc1 += row[h + 1] * W_enc[(h + 1) * NA + a];
    }
    g_encT[(b * NA + a) * NS + s] = acc0 + acc1;
}

// ---------------------------------------------------------------------------
// K1: fused attention for step t. One block per batch element, 256 threads.
//   dec = prev @ W_dec (coalesced over a)
//   energy[s] = sum_a tanh(encT[a][s] + dec[a]) * v[a]   (coalesced over s)
//   softmax (single warp) -> attn weights out
//   context[d] = sum_s aw[s] * enc[b,s,d]               (coalesced over d)
// ---------------------------------------------------------------------------
__global__ void __launch_bounds__(256) k_attn(int t,
                       const float* __restrict__ enc,
                       const float* __restrict__ dec_init,
                       const int* __restrict__ mask,
                       const float* __restrict__ W_dec,
                       const float* __restrict__ v,
                       float* __restrict__ attn_out) {
    const int b = blockIdx.x;
    const int tid = threadIdx.x;

    __shared__ __align__(16) float prev[DH];
    __shared__ float dec[NA];
    __shared__ float vsh[NA];
    __shared__ float epart[2][NS];
    __shared__ float e[NS];

    const float* pv = (t == 0) ? (dec_init + b * DH)
                               : (g_h + ((t - 1) * NB + b) * DH);
    prev[tid] = pv[tid];
    prev[tid + 256] = pv[tid + 256];
    vsh[tid] = v[tid];
    __syncthreads();

    // dec[a] = sum_h prev[h] * W_dec[h,a]  — coalesced across a, 2 accumulators
    {
        float acc0 = 0.f, acc1 = 0.f;
        const float* W0 = W_dec + tid;
#pragma unroll 16
        for (int h = 0; h < DH; h += 2) {
            acc0 += prev[h] * W0[h * NA];
            acc1 += prev[h + 1] * W0[(h + 1) * NA];
        }
        dec[tid] = acc0 + acc1;
    }
    __syncthreads();

    // energy partials: half = which 128 a-values, s = source position
    {
        const int half = tid >> 7;
        const int s = tid & 127;
        const float* et = g_encT + ((size_t)b * NA + half * 128) * NS + s;
        const float* dv = dec + half * 128;
        const float* vv = vsh + half * 128;
        float acc0 = 0.f, acc1 = 0.f;
#pragma unroll 8
        for (int a = 0; a < 128; a += 2) {
            acc0 += tanh_hw(et[a * NS] + dv[a]) * vv[a];
            acc1 += tanh_hw(et[(a + 1) * NS] + dv[a + 1]) * vv[a + 1];
        }
        epart[half][s] = acc0 + acc1;
    }
    __syncthreads();

    // softmax over 128 energies — warp 0 handles all (4 values per lane)
    if (tid < 32) {
        float en[4];
#pragma unroll
        for (int j = 0; j < 4; j++) {
            int s = tid + j * 32;
            float x = epart[0][s] + epart[1][s];
            if (mask[b * NS + s] == 0) x = -1e9f;
            en[j] = x;
        }
        float mx = fmaxf(fmaxf(en[0], en[1]), fmaxf(en[2], en[3]));
#pragma unroll
        for (int off = 16; off > 0; off >>= 1)
            mx = fmaxf(mx, __shfl_xor_sync(0xffffffffu, mx, off));
        float sum = 0.f;
#pragma unroll
        for (int j = 0; j < 4; j++) {
            en[j] = __expf(en[j] - mx);
            sum += en[j];
        }
#pragma unroll
        for (int off = 16; off > 0; off >>= 1)
            sum += __shfl_xor_sync(0xffffffffu, sum, off);
        const float inv = 1.0f / sum;
        float* aw_out = attn_out + ((size_t)(b * NT + t)) * NS;
#pragma unroll
        for (int j = 0; j < 4; j++) {
            float aw = en[j] * inv;
            e[tid + j * 32] = aw;
            aw_out[tid + j * 32] = aw;
        }
    }
    __syncthreads();

    // context[d] = sum_s aw[s] * enc[b,s,d]  — coalesced across d
#pragma unroll
    for (int rep = 0; rep < 2; rep++) {
        const int d = tid + rep * 256;
        const float* eb = enc + (size_t)b * NS * EH + d;
        float a0 = 0.f, a1 = 0.f, a2 = 0.f, a3 = 0.f;
#pragma unroll 4
        for (int s = 0; s < NS; s += 4) {
            a0 += e[s] * eb[s * EH];
            a1 += e[s + 1] * eb[(s + 1) * EH];
            a2 += e[s + 2] * eb[(s + 2) * EH];
            a3 += e[s + 3] * eb[(s + 3) * EH];
        }
        g_ctx[b * EH + d] = (a0 + a1) + (a2 + a3);
    }
}

// ---------------------------------------------------------------------------
// K2: GRU gates + state update for step t. float4 weight loads.
// grid = NB*16 blocks (block = (b, chunk of 32 hidden idx)), 256 threads.
// ---------------------------------------------------------------------------
__global__ void __launch_bounds__(256) k_gru(int t,
                      const int* __restrict__ y,
                      const float* __restrict__ dec_init,
                      const float* __restrict__ embedding,
                      const float* __restrict__ W_ih,
                      const float* __restrict__ W_hh,
                      const float* __restrict__ b_ih,
                      const float* __restrict__ b_hh) {
    const int b = blockIdx.x >> 4;
    const int i0 = (blockIdx.x & 15) * 32;
    const int tid = threadIdx.x;
    const int lane = tid & 31;
    const int w = tid >> 5;

    __shared__ __align__(16) float x[IND];
    __shared__ __align__(16) float prev[DH];

    const float* pv = (t == 0) ? (dec_init + b * DH)
                               : (g_h + ((t - 1) * NB + b) * DH);
    const int tok = y[b * NT + t];
    for (int i = tid; i < NE; i += 256) x[i] = embedding[(size_t)tok * NE + i];
    for (int i = tid; i < EH; i += 256) x[NE + i] = g_ctx[b * EH + i];
    for (int i = tid; i < DH; i += 256) prev[i] = pv[i];
    __syncthreads();

    const float4* xs4 = reinterpret_cast<const float4*>(x);
    const float4* ps4 = reinterpret_cast<const float4*>(prev);

#pragma unroll
    for (int ii = 0; ii < 4; ii++) {
        const int i = i0 + w * 4 + ii;
        float gx[3], gh[3];
#pragma unroll
        for (int g = 0; g < 3; g++) {
            const int row = g * DH + i;
            const float4* wi4 =
                reinterpret_cast<const float4*>(W_ih + (size_t)row * IND);
            const float4* wh4 =
                reinterpret_cast<const float4*>(W_hh + (size_t)row * DH);
            float ax = 0.f, ah = 0.f;
#pragma unroll
            for (int j = 0; j < IND / 128; j++) {  // 6
                float4 wv = wi4[j * 32 + lane];
                float4 xv = xs4[j * 32 + lane];
                ax += wv.x * xv.x + wv.y * xv.y + wv.z * xv.z + wv.w * xv.w;
            }
#pragma unroll
            for (int j = 0; j < DH / 128; j++) {  // 4
                float4 wv = wh4[j * 32 + lane];
                float4 hv = ps4[j * 32 + lane];
                ah += wv.x * hv.x + wv.y * hv.y + wv.z * hv.z + wv.w * hv.w;
            }
#pragma unroll
            for (int off = 16; off > 0; off >>= 1) {
                ax += __shfl_down_sync(0xffffffffu, ax, off);
                ah += __shfl_down_sync(0xffffffffu, ah, off);
            }
            gx[g] = ax;
            gh[g] = ah;
        }
        if (lane == 0) {
            float xr = gx[0] + b_ih[i],          hr = gh[0] + b_hh[i];
            float xz = gx[1] + b_ih[DH + i],     hz = gh[1] + b_hh[DH + i];
            float xn = gx[2] + b_ih[2 * DH + i], hn = gh[2] + b_hh[2 * DH + i];
            float r = fast_sigmoid(xr + hr);
            float z = fast_sigmoid(xz + hz);
            float n = fast_tanh(xn + r * hn);
            float p = prev[i];
            g_h[((size_t)t * NB + b) * DH + i] = (1.0f - z) * n + z * p;
        }
    }
}

// ---------------------------------------------------------------------------
// K3: batched FC:  out[(b,t), n] = h_all[(t,b), :] @ W_fc + b_fc
// M=2048, N=31999, K=512. 128x128x8 tiles, 8x8 per thread, f32x2 packed FMA.
// ---------------------------------------------------------------------------
constexpr int FBM = 128, FBN = 128, FBK = 8;

__global__ void __launch_bounds__(256) k_fc(const float* __restrict__ Wfc,
                                            const float* __restrict__ bfc,
                                            float* __restrict__ out) {
    __shared__ __align__(16) float As[FBK][FBM];
    __shared__ __align__(16) float Bs[FBK][FBN];

    const int n0 = blockIdx.x * FBN;
    const int m0 = blockIdx.y * FBM;
    const int tid = threadIdx.x;
    const int tx = tid & 15;
    const int ty = tid >> 4;
    const int am = tid >> 1;
    const int ak4 = (tid & 1) * 4;
    const int bk = tid >> 5;
    const int bn = (tid & 31) * 4;

    unsigned long long c2[2][2][2][4];
#pragma unroll
    for (int a = 0; a < 2; a++)
#pragma unroll
        for (int p = 0; p < 2; p++)
#pragma unroll
            for (int h = 0; h < 2; h++)
#pragma unroll
                for (int j = 0; j < 4; j++) c2[a][p][h][j] = 0ull;

    for (int kt = 0; kt < DH; kt += FBK) {
        float4 a4 = *reinterpret_cast<const float4*>(
            &g_h[(size_t)(m0 + am) * DH + kt + ak4]);
        As[ak4 + 0][am] = a4.x;
        As[ak4 + 1][am] = a4.y;
        As[ak4 + 2][am] = a4.z;
        As[ak4 + 3][am] = a4.w;
#pragma unroll
        for (int q = 0; q < 4; q++) {
            int n = n0 + bn + q;
            Bs[bk][bn + q] = (n < NV) ? Wfc[(size_t)(kt + bk) * NV + n] : 0.f;
        }
        __syncthreads();

#pragma unroll
        for (int kk = 0; kk < FBK; kk++) {
            unsigned long long a2[2][2];
            float4 bv[2];
#pragma unroll
            for (int h = 0; h < 2; h++) {
                float4 av = *reinterpret_cast<const float4*>(&As[kk][h * 64 + ty * 4]);
                a2[h][0] = pack2(av.x, av.y);
                a2[h][1] = pack2(av.z, av.w);
                bv[h] = *reinterpret_cast<const float4*>(&Bs[kk][h * 64 + tx * 4]);
            }
#pragma unroll
            for (int hb = 0; hb < 2; hb++) {
                float bj[4] = {bv[hb].x, bv[hb].y, bv[hb].z, bv[hb].w};
#pragma unroll
                for (int j = 0; j < 4; j++) {
                    unsigned long long b2 = pack2(bj[j], bj[j]);
#pragma unroll
                    for (int ha = 0; ha < 2; ha++)
#pragma unroll
                        for (int ip = 0; ip < 2; ip++)
                            ffma2(c2[ha][ip][hb][j], a2[ha][ip], b2);
                }
            }
        }
        __syncthreads();
    }

#pragma unroll
    for (int ha = 0; ha < 2; ha++)
#pragma unroll
        for (int ip = 0; ip < 2; ip++) {
            const int m = m0 + ha * 64 + ty * 4 + ip * 2;
#pragma unroll
            for (int hb = 0; hb < 2; hb++)
#pragma unroll
                for (int j = 0; j < 4; j++) {
                    const int n = n0 + hb * 64 + tx * 4 + j;
                    if (n < NV) {
                        float lo, hi;
                        unpack2(c2[ha][ip][hb][j], lo, hi);
                        const float bias = bfc[n];
                        const int t1 = m >> 5, b1 = m & 31;
                        const int t2 = (m + 1) >> 5, b2i = (m + 1) & 31;
                        out[((size_t)(b1 * NT + t1)) * NV + n] = lo + bias;
                        out[((size_t)(b2i * NT + t2)) * NV + n] = hi + bias;
                    }
                }
        }
}

// ---------------------------------------------------------------------------
// Launch
// ---------------------------------------------------------------------------
extern "C" void kernel_launch(void* const* d_in, const int* in_sizes, int n_in,
                              void* d_out, int out_size) {
    const int* y = (const int*)d_in[0];
    const float* enc = (const float*)d_in[1];
    const float* dec_init = (const float*)d_in[2];
    const int* mask = (const int*)d_in[3];
    const float* emb = (const float*)d_in[4];
    const float* W_enc = (const float*)d_in[5];
    const float* W_dec = (const float*)d_in[6];
    const float* v = (const float*)d_in[7];
    const float* W_ih = (const float*)d_in[8];
    const float* W_hh = (const float*)d_in[9];
    const float* b_ih = (const float*)d_in[10];
    const float* b_hh = (const float*)d_in[11];
    const float* W_fc = (const float*)d_in[12];
    const float* b_fc = (const float*)d_in[13];

    float* out = (float*)d_out;
    float* attn_out = out + (size_t)NB * NT * NV;

    k_encproj<<<NB * NS, 256>>>(enc, W_enc);
    for (int t = 0; t < NT; t++) {
        k_attn<<<NB, 256>>>(t, enc, dec_init, mask, W_dec, v, attn_out);
        k_gru<<<NB * 16, 256>>>(t, y, dec_init, emb, W_ih, W_hh, b_ih, b_hh);
    }
    dim3 gfc((NV + FBN - 1) / FBN, (NB * NT) / FBM);
    k_fc<<<gfc, 256>>>(W_fc, b_fc, out);
}

// round 3
// speedup vs baseline: 1.4370x; 1.2182x over previous
#include <cuda_runtime.h>

// ---------------------------------------------------------------------------
// Problem constants
// ---------------------------------------------------------------------------
namespace {
constexpr int NB = 32;       // batch
constexpr int NT = 64;       // decode steps
constexpr int NS = 128;      // source length
constexpr int EH = 512;      // encoder hidden
constexpr int DH = 512;      // decoder hidden
constexpr int NA = 256;      // attention dim
constexpr int NE = 256;      // embedding dim
constexpr int NV = 31999;    // vocab - 1 (FC output width)
constexpr int IND = NE + EH; // 768, GRU input dim
}

// ---------------------------------------------------------------------------
// Device scratch (no allocations allowed)
// ---------------------------------------------------------------------------
__device__ __align__(16) float g_encT[NB * NA * NS];   // enc_proj transposed [b][a][s]
__device__ __align__(16) float g_h[NT * NB * DH];      // h_t for all steps
__device__ __align__(16) float g_ctx[NB * EH];         // per-step context
__device__ __align__(16) float g_epart[NB * 4 * NS];   // energy partials [b][atile][s]

// ---------------------------------------------------------------------------
// math helpers
// ---------------------------------------------------------------------------
__device__ __forceinline__ unsigned long long pack2(float lo, float hi) {
    unsigned long long r;
    asm("mov.b64 %0, {%1, %2};" : "=l"(r) : "f"(lo), "f"(hi));
    return r;
}
__device__ __forceinline__ void ffma2(unsigned long long& c, unsigned long long a,
                                      unsigned long long b) {
    asm("fma.rn.f32x2 %0, %1, %2, %0;" : "+l"(c) : "l"(a), "l"(b));
}
__device__ __forceinline__ void unpack2(unsigned long long v, float& lo, float& hi) {
    asm("mov.b64 {%0, %1}, %2;" : "=f"(lo), "=f"(hi) : "l"(v));
}
__device__ __forceinline__ float tanh_hw(float x) {  // MUFU.TANH
    float y;
    asm("tanh.approx.f32 %0, %1;" : "=f"(y) : "f"(x));
    return y;
}
__device__ __forceinline__ float fast_tanh(float x) {  // precise path (GRU)
    float e2 = __expf(2.0f * x);
    return 1.0f - 2.0f / (e2 + 1.0f);
}
__device__ __forceinline__ float fast_sigmoid(float x) {
    return 1.0f / (1.0f + __expf(-x));
}

// ---------------------------------------------------------------------------
// K0: enc_projT[b][a][s] = sum_h enc[b,s,h] * W_enc[h,a]   (once)
// ---------------------------------------------------------------------------
__global__ void k_encproj(const float* __restrict__ enc,
                          const float* __restrict__ W_enc) {
    const int rs = blockIdx.x;  // b*NS + s
    const int b = rs >> 7;
    const int s = rs & 127;
    __shared__ float row[EH];
    for (int i = threadIdx.x; i < EH; i += 256) row[i] = enc[rs * EH + i];
    __syncthreads();
    const int a = threadIdx.x;
    float acc0 = 0.f, acc1 = 0.f;
#pragma unroll 8
    for (int h = 0; h < EH; h += 2) {
        acc0 += row[h] * W_enc[h * NA + a];
        acc1 += row[h + 1] * W_enc[(h + 1) * NA + a];
    }
    g_encT[(b * NA + a) * NS + s] = acc0 + acc1;
}

// ---------------------------------------------------------------------------
// K1: energy partials for step t.  grid = NB*4 (block = (b, a-tile of 64)).
//   Phase 1: dec[a] = prev @ W_dec[:, a-tile]   (block-local)
//   Phase 2: epart[b][tile][s] = sum_{a in tile} tanh(encT[a][s]+dec[a])*v[a]
// ---------------------------------------------------------------------------
__global__ void __launch_bounds__(256) k_energy(int t,
                        const float* __restrict__ dec_init,
                        const float* __restrict__ W_dec,
                        const float* __restrict__ v) {
    const int b = blockIdx.x >> 2;
    const int at = blockIdx.x & 3;
    const int a0 = at * 64;
    const int tid = threadIdx.x;

    __shared__ __align__(16) float prev[DH];
    __shared__ float dpart[4][64];
    __shared__ float decs[64];
    __shared__ float vsh[64];
    __shared__ float ep2[2][NS];

    const float* pv = (t == 0) ? (dec_init + b * DH)
                               : (g_h + ((t - 1) * NB + b) * DH);
    prev[tid] = pv[tid];
    prev[tid + 256] = pv[tid + 256];
    if (tid < 64) vsh[tid] = v[a0 + tid];
    __syncthreads();

    // Phase 1: dec for the 64 a-values of this tile.
    // thread = (hq = tid>>6 in [0,4), j = tid&63): partial over 128 h.
    {
        const int j = tid & 63;
        const int hq = tid >> 6;
        const float* W0 = W_dec + (size_t)(hq * 128) * NA + a0 + j;
        const float* pr = prev + hq * 128;
        float c0 = 0.f, c1 = 0.f, c2 = 0.f, c3 = 0.f;
#pragma unroll 8
        for (int h = 0; h < 128; h += 4) {
            c0 += pr[h] * W0[h * NA];
            c1 += pr[h + 1] * W0[(h + 1) * NA];
            c2 += pr[h + 2] * W0[(h + 2) * NA];
            c3 += pr[h + 3] * W0[(h + 3) * NA];
        }
        dpart[hq][j] = (c0 + c1) + (c2 + c3);
    }
    __syncthreads();
    if (tid < 64)
        decs[tid] = (dpart[0][tid] + dpart[1][tid]) + (dpart[2][tid] + dpart[3][tid]);
    __syncthreads();

    // Phase 2: energy partial over this 64-a tile for all 128 s.
    // thread = (ah = tid>>7 in [0,2), s = tid&127): 32 a per thread.
    {
        const int ah = tid >> 7;
        const int s = tid & 127;
        const float* et = g_encT + ((size_t)b * NA + a0 + ah * 32) * NS + s;
        const float* dv = decs + ah * 32;
        const float* vv = vsh + ah * 32;
        float c0 = 0.f, c1 = 0.f, c2 = 0.f, c3 = 0.f;
#pragma unroll
        for (int a = 0; a < 32; a += 4) {
            c0 += tanh_hw(et[(a + 0) * NS] + dv[a + 0]) * vv[a + 0];
            c1 += tanh_hw(et[(a + 1) * NS] + dv[a + 1]) * vv[a + 1];
            c2 += tanh_hw(et[(a + 2) * NS] + dv[a + 2]) * vv[a + 2];
            c3 += tanh_hw(et[(a + 3) * NS] + dv[a + 3]) * vv[a + 3];
        }
        ep2[ah][s] = (c0 + c1) + (c2 + c3);
    }
    __syncthreads();
    if (tid < NS)
        g_epart[(b * 4 + at) * NS + tid] = ep2[0][tid] + ep2[1][tid];
}

// ---------------------------------------------------------------------------
// K2: softmax + context for step t.  grid = NB*4 (block = (b, d-tile of 128)).
//   energy = sum of 4 partials; softmax (dup per block, cheap);
//   context[d-tile] = aw @ enc[b,:,d-tile];  aw out written by d-tile 0.
// ---------------------------------------------------------------------------
__global__ void __launch_bounds__(256) k_ctx(int t,
                     const float* __restrict__ enc,
                     const int* __restrict__ mask,
                     float* __restrict__ attn_out) {
    const int b = blockIdx.x >> 2;
    const int dt = blockIdx.x & 3;
    const int d0 = dt * 128;
    const int tid = threadIdx.x;

    __shared__ float aw[NS];
    __shared__ float cpart[2][128];

    // softmax over 128 energies — warp 0, 4 values per lane
    if (tid < 32) {
        float en[4];
#pragma unroll
        for (int j = 0; j < 4; j++) {
            const int s = tid + j * 32;
            const float* gp = g_epart + (b * 4) * NS + s;
            float x = (gp[0] + gp[NS]) + (gp[2 * NS] + gp[3 * NS]);
            if (mask[b * NS + s] == 0) x = -1e9f;
            en[j] = x;
        }
        float mx = fmaxf(fmaxf(en[0], en[1]), fmaxf(en[2], en[3]));
#pragma unroll
        for (int off = 16; off > 0; off >>= 1)
            mx = fmaxf(mx, __shfl_xor_sync(0xffffffffu, mx, off));
        float sum = 0.f;
#pragma unroll
        for (int j = 0; j < 4; j++) {
            en[j] = __expf(en[j] - mx);
            sum += en[j];
        }
#pragma unroll
        for (int off = 16; off > 0; off >>= 1)
            sum += __shfl_xor_sync(0xffffffffu, sum, off);
        const float inv = 1.0f / sum;
#pragma unroll
        for (int j = 0; j < 4; j++) {
            const float w = en[j] * inv;
            aw[tid + j * 32] = w;
            if (dt == 0)
                attn_out[((size_t)(b * NT + t)) * NS + tid + j * 32] = w;
        }
    }
    __syncthreads();

    // context: thread = (sh = tid>>7, d = d0 + tid&127); 64 s per thread
    {
        const int sh = tid >> 7;
        const int d = d0 + (tid & 127);
        const float* eb = enc + ((size_t)b * NS + sh * 64) * EH + d;
        const float* w = aw + sh * 64;
        float c0 = 0.f, c1 = 0.f, c2 = 0.f, c3 = 0.f;
#pragma unroll 4
        for (int s = 0; s < 64; s += 4) {
            c0 += w[s + 0] * eb[(s + 0) * EH];
            c1 += w[s + 1] * eb[(s + 1) * EH];
            c2 += w[s + 2] * eb[(s + 2) * EH];
            c3 += w[s + 3] * eb[(s + 3) * EH];
        }
        cpart[tid >> 7][tid & 127] = (c0 + c1) + (c2 + c3);
    }
    __syncthreads();
    if (tid < 128) g_ctx[b * EH + d0 + tid] = cpart[0][tid] + cpart[1][tid];
}

// ---------------------------------------------------------------------------
// K3: GRU gates + state update for step t. float4 weight loads.
// grid = NB*16 blocks (block = (b, chunk of 32 hidden idx)), 256 threads.
// ---------------------------------------------------------------------------
__global__ void __launch_bounds__(256) k_gru(int t,
                      const int* __restrict__ y,
                      const float* __restrict__ dec_init,
                      const float* __restrict__ embedding,
                      const float* __restrict__ W_ih,
                      const float* __restrict__ W_hh,
                      const float* __restrict__ b_ih,
                      const float* __restrict__ b_hh) {
    const int b = blockIdx.x >> 4;
    const int i0 = (blockIdx.x & 15) * 32;
    const int tid = threadIdx.x;
    const int lane = tid & 31;
    const int w = tid >> 5;

    __shared__ __align__(16) float x[IND];
    __shared__ __align__(16) float prev[DH];

    const float* pv = (t == 0) ? (dec_init + b * DH)
                               : (g_h + ((t - 1) * NB + b) * DH);
    const int tok = y[b * NT + t];
    for (int i = tid; i < NE; i += 256) x[i] = embedding[(size_t)tok * NE + i];
    for (int i = tid; i < EH; i += 256) x[NE + i] = g_ctx[b * EH + i];
    for (int i = tid; i < DH; i += 256) prev[i] = pv[i];
    __syncthreads();

    const float4* xs4 = reinterpret_cast<const float4*>(x);
    const float4* ps4 = reinterpret_cast<const float4*>(prev);

#pragma unroll
    for (int ii = 0; ii < 4; ii++) {
        const int i = i0 + w * 4 + ii;
        float gx[3], gh[3];
#pragma unroll
        for (int g = 0; g < 3; g++) {
            const int row = g * DH + i;
            const float4* wi4 =
                reinterpret_cast<const float4*>(W_ih + (size_t)row * IND);
            const float4* wh4 =
                reinterpret_cast<const float4*>(W_hh + (size_t)row * DH);
            float ax = 0.f, ah = 0.f;
#pragma unroll
            for (int j = 0; j < IND / 128; j++) {  // 6
                float4 wv = wi4[j * 32 + lane];
                float4 xv = xs4[j * 32 + lane];
                ax += wv.x * xv.x + wv.y * xv.y + wv.z * xv.z + wv.w * xv.w;
            }
#pragma unroll
            for (int j = 0; j < DH / 128; j++) {  // 4
                float4 wv = wh4[j * 32 + lane];
                float4 hv = ps4[j * 32 + lane];
                ah += wv.x * hv.x + wv.y * hv.y + wv.z * hv.z + wv.w * hv.w;
            }
#pragma unroll
            for (int off = 16; off > 0; off >>= 1) {
                ax += __shfl_down_sync(0xffffffffu, ax, off);
                ah += __shfl_down_sync(0xffffffffu, ah, off);
            }
            gx[g] = ax;
            gh[g] = ah;
        }
        if (lane == 0) {
            float xr = gx[0] + b_ih[i],          hr = gh[0] + b_hh[i];
            float xz = gx[1] + b_ih[DH + i],     hz = gh[1] + b_hh[DH + i];
            float xn = gx[2] + b_ih[2 * DH + i], hn = gh[2] + b_hh[2 * DH + i];
            float r = fast_sigmoid(xr + hr);
            float z = fast_sigmoid(xz + hz);
            float n = fast_tanh(xn + r * hn);
            float p = prev[i];
            g_h[((size_t)t * NB + b) * DH + i] = (1.0f - z) * n + z * p;
        }
    }
}

// ---------------------------------------------------------------------------
// K4: batched FC:  out[(b,t), n] = h_all[(t,b), :] @ W_fc + b_fc
// M=2048, N=31999, K=512. 128x128x8 tiles, 8x8 per thread, f32x2 packed FMA.
// ---------------------------------------------------------------------------
constexpr int FBM = 128, FBN = 128, FBK = 8;

__global__ void __launch_bounds__(256) k_fc(const float* __restrict__ Wfc,
                                            const float* __restrict__ bfc,
                                            float* __restrict__ out) {
    __shared__ __align__(16) float As[FBK][FBM];
    __shared__ __align__(16) float Bs[FBK][FBN];

    const int n0 = blockIdx.x * FBN;
    const int m0 = blockIdx.y * FBM;
    const int tid = threadIdx.x;
    const int tx = tid & 15;
    const int ty = tid >> 4;
    const int am = tid >> 1;
    const int ak4 = (tid & 1) * 4;
    const int bk = tid >> 5;
    const int bn = (tid & 31) * 4;

    unsigned long long c2[2][2][2][4];
#pragma unroll
    for (int a = 0; a < 2; a++)
#pragma unroll
        for (int p = 0; p < 2; p++)
#pragma unroll
            for (int h = 0; h < 2; h++)
#pragma unroll
                for (int j = 0; j < 4; j++) c2[a][p][h][j] = 0ull;

    for (int kt = 0; kt < DH; kt += FBK) {
        float4 a4 = *reinterpret_cast<const float4*>(
            &g_h[(size_t)(m0 + am) * DH + kt + ak4]);
        As[ak4 + 0][am] = a4.x;
        As[ak4 + 1][am] = a4.y;
        As[ak4 + 2][am] = a4.z;
        As[ak4 + 3][am] = a4.w;
#pragma unroll
        for (int q = 0; q < 4; q++) {
            int n = n0 + bn + q;
            Bs[bk][bn + q] = (n < NV) ? Wfc[(size_t)(kt + bk) * NV + n] : 0.f;
        }
        __syncthreads();

#pragma unroll
        for (int kk = 0; kk < FBK; kk++) {
            unsigned long long a2[2][2];
            float4 bv[2];
#pragma unroll
            for (int h = 0; h < 2; h++) {
                float4 av = *reinterpret_cast<const float4*>(&As[kk][h * 64 + ty * 4]);
                a2[h][0] = pack2(av.x, av.y);
                a2[h][1] = pack2(av.z, av.w);
                bv[h] = *reinterpret_cast<const float4*>(&Bs[kk][h * 64 + tx * 4]);
            }
#pragma unroll
            for (int hb = 0; hb < 2; hb++) {
                float bj[4] = {bv[hb].x, bv[hb].y, bv[hb].z, bv[hb].w};
#pragma unroll
                for (int j = 0; j < 4; j++) {
                    unsigned long long b2 = pack2(bj[j], bj[j]);
#pragma unroll
                    for (int ha = 0; ha < 2; ha++)
#pragma unroll
                        for (int ip = 0; ip < 2; ip++)
                            ffma2(c2[ha][ip][hb][j], a2[ha][ip], b2);
                }
            }
        }
        __syncthreads();
    }

#pragma unroll
    for (int ha = 0; ha < 2; ha++)
#pragma unroll
        for (int ip = 0; ip < 2; ip++) {
            const int m = m0 + ha * 64 + ty * 4 + ip * 2;
#pragma unroll
            for (int hb = 0; hb < 2; hb++)
#pragma unroll
                for (int j = 0; j < 4; j++) {
                    const int n = n0 + hb * 64 + tx * 4 + j;
                    if (n < NV) {
                        float lo, hi;
                        unpack2(c2[ha][ip][hb][j], lo, hi);
                        const float bias = bfc[n];
                        const int t1 = m >> 5, b1 = m & 31;
                        const int t2 = (m + 1) >> 5, b2i = (m + 1) & 31;
                        out[((size_t)(b1 * NT + t1)) * NV + n] = lo + bias;
                        out[((size_t)(b2i * NT + t2)) * NV + n] = hi + bias;
                    }
                }
        }
}

// ---------------------------------------------------------------------------
// Launch
// ---------------------------------------------------------------------------
extern "C" void kernel_launch(void* const* d_in, const int* in_sizes, int n_in,
                              void* d_out, int out_size) {
    const int* y = (const int*)d_in[0];
    const float* enc = (const float*)d_in[1];
    const float* dec_init = (const float*)d_in[2];
    const int* mask = (const int*)d_in[3];
    const float* emb = (const float*)d_in[4];
    const float* W_enc = (const float*)d_in[5];
    const float* W_dec = (const float*)d_in[6];
    const float* v = (const float*)d_in[7];
    const float* W_ih = (const float*)d_in[8];
    const float* W_hh = (const float*)d_in[9];
    const float* b_ih = (const float*)d_in[10];
    const float* b_hh = (const float*)d_in[11];
    const float* W_fc = (const float*)d_in[12];
    const float* b_fc = (const float*)d_in[13];

    float* out = (float*)d_out;
    float* attn_out = out + (size_t)NB * NT * NV;

    k_encproj<<<NB * NS, 256>>>(enc, W_enc);
    for (int t = 0; t < NT; t++) {
        k_energy<<<NB * 4, 256>>>(t, dec_init, W_dec, v);
        k_ctx<<<NB * 4, 256>>>(t, enc, mask, attn_out);
        k_gru<<<NB * 16, 256>>>(t, y, dec_init, emb, W_ih, W_hh, b_ih, b_hh);
    }
    dim3 gfc((NV + FBN - 1) / FBN, (NB * NT) / FBM);
    k_fc<<<gfc, 256>>>(W_fc, b_fc, out);
}

// round 4
// speedup vs baseline: 1.9159x; 1.3332x over previous
#include <cuda_runtime.h>

// ---------------------------------------------------------------------------
// Problem constants
// ---------------------------------------------------------------------------
namespace {
constexpr int NB = 32;       // batch
constexpr int NT = 64;       // decode steps
constexpr int NS = 128;      // source length
constexpr int EH = 512;      // encoder hidden
constexpr int DH = 512;      // decoder hidden
constexpr int NA = 256;      // attention dim
constexpr int NE = 256;      // embedding dim
constexpr int NV = 31999;    // vocab - 1 (FC output width)
constexpr int IND = NE + EH; // 768, GRU input dim
constexpr int NG = 3 * DH;   // 1536 gate rows
constexpr int NKC = 4;       // K-chunks in k_gates
}

// ---------------------------------------------------------------------------
// Device scratch (no allocations allowed)
// ---------------------------------------------------------------------------
__device__ __align__(16) float g_encT[NB * NA * NS];        // enc_proj [b][a][s]
__device__ __align__(16) float g_h[NT * NB * DH];           // h_t for all steps
__device__ __align__(16) float g_ctx[NB * EH];              // per-step context
__device__ __align__(16) float g_epart[NB * 4 * NS];        // energy partials
__device__ __align__(16) float g_wihT[NE * NG];             // W_ih[:, :256] transposed
__device__ __align__(16) float g_gxemb[NT * NG * NB];       // [t][row][b], 12.6MB
__device__ __align__(16) float g_gpart[NKC * 2 * NG * NB];  // [kc][row 0..3071][b]

// ---------------------------------------------------------------------------
// math helpers
// ---------------------------------------------------------------------------
__device__ __forceinline__ unsigned long long pack2(float lo, float hi) {
    unsigned long long r;
    asm("mov.b64 %0, {%1, %2};" : "=l"(r) : "f"(lo), "f"(hi));
    return r;
}
__device__ __forceinline__ void ffma2(unsigned long long& c, unsigned long long a,
                                      unsigned long long b) {
    asm("fma.rn.f32x2 %0, %1, %2, %0;" : "+l"(c) : "l"(a), "l"(b));
}
__device__ __forceinline__ void unpack2(unsigned long long v, float& lo, float& hi) {
    asm("mov.b64 {%0, %1}, %2;" : "=f"(lo), "=f"(hi) : "l"(v));
}
__device__ __forceinline__ float tanh_hw(float x) {  // MUFU.TANH (attention only)
    float y;
    asm("tanh.approx.f32 %0, %1;" : "=f"(y) : "f"(x));
    return y;
}
__device__ __forceinline__ float fast_tanh(float x) {  // precise path (GRU)
    float e2 = __expf(2.0f * x);
    return 1.0f - 2.0f / (e2 + 1.0f);
}
__device__ __forceinline__ float fast_sigmoid(float x) {
    return 1.0f / (1.0f + __expf(-x));
}

// ---------------------------------------------------------------------------
// K-pre-a: transpose W_ih[:, 0:256] -> g_wihT[256][1536]
// ---------------------------------------------------------------------------
__global__ void k_trih(const float* __restrict__ W_ih) {
    __shared__ float tile[32][33];
    const int n0 = blockIdx.x * 32;  // gate-row block (48)
    const int k0 = blockIdx.y * 32;  // emb-col block (8)
    const int tx = threadIdx.x & 31;
    const int ty0 = threadIdx.x >> 5;  // 0..7
#pragma unroll
    for (int i = 0; i < 32; i += 8)
        tile[ty0 + i][tx] = W_ih[(size_t)(n0 + ty0 + i) * IND + k0 + tx];
    __syncthreads();
#pragma unroll
    for (int i = 0; i < 32; i += 8)
        g_wihT[(size_t)(k0 + ty0 + i) * NG + n0 + tx] = tile[tx][ty0 + i];
}

// ---------------------------------------------------------------------------
// K-pre-b: enc_projT[b][a][s]
// ---------------------------------------------------------------------------
__global__ void k_encproj(const float* __restrict__ enc,
                          const float* __restrict__ W_enc) {
    const int rs = blockIdx.x;
    const int b = rs >> 7;
    const int s = rs & 127;
    __shared__ float row[EH];
    for (int i = threadIdx.x; i < EH; i += 256) row[i] = enc[rs * EH + i];
    __syncthreads();
    const int a = threadIdx.x;
    float acc0 = 0.f, acc1 = 0.f;
#pragma unroll 8
    for (int h = 0; h < EH; h += 2) {
        acc0 += row[h] * W_enc[h * NA + a];
        acc1 += row[h + 1] * W_enc[(h + 1) * NA + a];
    }
    g_encT[(b * NA + a) * NS + s] = acc0 + acc1;
}

// ---------------------------------------------------------------------------
// K-pre-c: gx_emb[t][n][b] = emb[y[b][t]] . W_ih[n][:256]   (all steps at once)
// GEMM M=2048 (t,b), N=1536, K=256; A gathered from embedding, B = g_wihT.
// ---------------------------------------------------------------------------
constexpr int FBM = 128, FBN = 128, FBK = 8;

__global__ void __launch_bounds__(256) k_gxemb(const int* __restrict__ y,
                                               const float* __restrict__ embedding) {
    __shared__ __align__(16) float As[FBK][FBM];
    __shared__ __align__(16) float Bs[FBK][FBN];

    const int n0 = blockIdx.x * FBN;
    const int m0 = blockIdx.y * FBM;
    const int tid = threadIdx.x;
    const int tx = tid & 15;
    const int ty = tid >> 4;
    const int am = tid >> 1;
    const int ak4 = (tid & 1) * 4;
    const int bk = tid >> 5;
    const int bn = (tid & 31) * 4;

    // token for this thread's A row (fixed across k-loop)
    const int m = m0 + am;
    const int tok = y[(m & 31) * NT + (m >> 5)];
    const float* arow = embedding + (size_t)tok * NE;

    unsigned long long c2[2][2][2][4];
#pragma unroll
    for (int a = 0; a < 2; a++)
#pragma unroll
        for (int p = 0; p < 2; p++)
#pragma unroll
            for (int h = 0; h < 2; h++)
#pragma unroll
                for (int j = 0; j < 4; j++) c2[a][p][h][j] = 0ull;

    for (int kt = 0; kt < NE; kt += FBK) {
        float4 a4 = *reinterpret_cast<const float4*>(arow + kt + ak4);
        As[ak4 + 0][am] = a4.x;
        As[ak4 + 1][am] = a4.y;
        As[ak4 + 2][am] = a4.z;
        As[ak4 + 3][am] = a4.w;
        float4 b4 = *reinterpret_cast<const float4*>(
            &g_wihT[(size_t)(kt + bk) * NG + n0 + bn]);
        Bs[bk][bn + 0] = b4.x;
        Bs[bk][bn + 1] = b4.y;
        Bs[bk][bn + 2] = b4.z;
        Bs[bk][bn + 3] = b4.w;
        __syncthreads();
#pragma unroll
        for (int kk = 0; kk < FBK; kk++) {
            unsigned long long a2[2][2];
            float4 bv[2];
#pragma unroll
            for (int h = 0; h < 2; h++) {
                float4 av = *reinterpret_cast<const float4*>(&As[kk][h * 64 + ty * 4]);
                a2[h][0] = pack2(av.x, av.y);
                a2[h][1] = pack2(av.z, av.w);
                bv[h] = *reinterpret_cast<const float4*>(&Bs[kk][h * 64 + tx * 4]);
            }
#pragma unroll
            for (int hb = 0; hb < 2; hb++) {
                float bj[4] = {bv[hb].x, bv[hb].y, bv[hb].z, bv[hb].w};
#pragma unroll
                for (int j = 0; j < 4; j++) {
                    unsigned long long b2 = pack2(bj[j], bj[j]);
#pragma unroll
                    for (int ha = 0; ha < 2; ha++)
#pragma unroll
                        for (int ip = 0; ip < 2; ip++)
                            ffma2(c2[ha][ip][hb][j], a2[ha][ip], b2);
                }
            }
        }
        __syncthreads();
    }

    // store: C[m][n] -> g_gxemb[(t*NG + n)*NB + b];  m even -> (b, b+1) adjacent
#pragma unroll
    for (int ha = 0; ha < 2; ha++)
#pragma unroll
        for (int ip = 0; ip < 2; ip++) {
            const int mm = m0 + ha * 64 + ty * 4 + ip * 2;
            const int tt = mm >> 5, bb = mm & 31;
#pragma unroll
            for (int hb = 0; hb < 2; hb++)
#pragma unroll
                for (int j = 0; j < 4; j++) {
                    const int n = n0 + hb * 64 + tx * 4 + j;
                    float lo, hi;
                    unpack2(c2[ha][ip][hb][j], lo, hi);
                    float2* dst = reinterpret_cast<float2*>(
                        &g_gxemb[((size_t)tt * NG + n) * NB + bb]);
                    *dst = make_float2(lo, hi);
                }
        }
}

// ---------------------------------------------------------------------------
// K1: energy partials for step t.  grid = NB*4 (block = (b, a-tile of 64)).
// ---------------------------------------------------------------------------
__global__ void __launch_bounds__(256) k_energy(int t,
                        const float* __restrict__ dec_init,
                        const float* __restrict__ W_dec,
                        const float* __restrict__ v) {
    const int b = blockIdx.x >> 2;
    const int at = blockIdx.x & 3;
    const int a0 = at * 64;
    const int tid = threadIdx.x;

    __shared__ __align__(16) float prev[DH];
    __shared__ float dpart[4][64];
    __shared__ float decs[64];
    __shared__ float vsh[64];
    __shared__ float ep2[2][NS];

    const float* pv = (t == 0) ? (dec_init + b * DH)
                               : (g_h + ((t - 1) * NB + b) * DH);
    prev[tid] = pv[tid];
    prev[tid + 256] = pv[tid + 256];
    if (tid < 64) vsh[tid] = v[a0 + tid];
    __syncthreads();

    {
        const int j = tid & 63;
        const int hq = tid >> 6;
        const float* W0 = W_dec + (size_t)(hq * 128) * NA + a0 + j;
        const float* pr = prev + hq * 128;
        float c0 = 0.f, c1 = 0.f, c2 = 0.f, c3 = 0.f;
#pragma unroll 8
        for (int h = 0; h < 128; h += 4) {
            c0 += pr[h] * W0[h * NA];
            c1 += pr[h + 1] * W0[(h + 1) * NA];
            c2 += pr[h + 2] * W0[(h + 2) * NA];
            c3 += pr[h + 3] * W0[(h + 3) * NA];
        }
        dpart[hq][j] = (c0 + c1) + (c2 + c3);
    }
    __syncthreads();
    if (tid < 64)
        decs[tid] = (dpart[0][tid] + dpart[1][tid]) + (dpart[2][tid] + dpart[3][tid]);
    __syncthreads();

    {
        const int ah = tid >> 7;
        const int s = tid & 127;
        const float* et = g_encT + ((size_t)b * NA + a0 + ah * 32) * NS + s;
        const float* dv = decs + ah * 32;
        const float* vv = vsh + ah * 32;
        float c0 = 0.f, c1 = 0.f, c2 = 0.f, c3 = 0.f;
#pragma unroll
        for (int a = 0; a < 32; a += 4) {
            c0 += tanh_hw(et[(a + 0) * NS] + dv[a + 0]) * vv[a + 0];
            c1 += tanh_hw(et[(a + 1) * NS] + dv[a + 1]) * vv[a + 1];
            c2 += tanh_hw(et[(a + 2) * NS] + dv[a + 2]) * vv[a + 2];
            c3 += tanh_hw(et[(a + 3) * NS] + dv[a + 3]) * vv[a + 3];
        }
        ep2[ah][s] = (c0 + c1) + (c2 + c3);
    }
    __syncthreads();
    if (tid < NS)
        g_epart[(b * 4 + at) * NS + tid] = ep2[0][tid] + ep2[1][tid];
}

// ---------------------------------------------------------------------------
// K2: softmax + context for step t.  grid = NB*4 (block = (b, d-tile of 128)).
// ---------------------------------------------------------------------------
__global__ void __launch_bounds__(256) k_ctx(int t,
                     const float* __restrict__ enc,
                     const int* __restrict__ mask,
                     float* __restrict__ attn_out) {
    const int b = blockIdx.x >> 2;
    const int dt = blockIdx.x & 3;
    const int d0 = dt * 128;
    const int tid = threadIdx.x;

    __shared__ float aw[NS];
    __shared__ float cpart[2][128];

    if (tid < 32) {
        float en[4];
#pragma unroll
        for (int j = 0; j < 4; j++) {
            const int s = tid + j * 32;
            const float* gp = g_epart + (b * 4) * NS + s;
            float x = (gp[0] + gp[NS]) + (gp[2 * NS] + gp[3 * NS]);
            if (mask[b * NS + s] == 0) x = -1e9f;
            en[j] = x;
        }
        float mx = fmaxf(fmaxf(en[0], en[1]), fmaxf(en[2], en[3]));
#pragma unroll
        for (int off = 16; off > 0; off >>= 1)
            mx = fmaxf(mx, __shfl_xor_sync(0xffffffffu, mx, off));
        float sum = 0.f;
#pragma unroll
        for (int j = 0; j < 4; j++) {
            en[j] = __expf(en[j] - mx);
            sum += en[j];
        }
#pragma unroll
        for (int off = 16; off > 0; off >>= 1)
            sum += __shfl_xor_sync(0xffffffffu, sum, off);
        const float inv = 1.0f / sum;
#pragma unroll
        for (int j = 0; j < 4; j++) {
            const float w = en[j] * inv;
            aw[tid + j * 32] = w;
            if (dt == 0)
                attn_out[((size_t)(b * NT + t)) * NS + tid + j * 32] = w;
        }
    }
    __syncthreads();

    {
        const int sh = tid >> 7;
        const int d = d0 + (tid & 127);
        const float* eb = enc + ((size_t)b * NS + sh * 64) * EH + d;
        const float* w = aw + sh * 64;
        float c0 = 0.f, c1 = 0.f, c2 = 0.f, c3 = 0.f;
#pragma unroll 4
        for (int s = 0; s < 64; s += 4) {
            c0 += w[s + 0] * eb[(s + 0) * EH];
            c1 += w[s + 1] * eb[(s + 1) * EH];
            c2 += w[s + 2] * eb[(s + 2) * EH];
            c3 += w[s + 3] * eb[(s + 3) * EH];
        }
        cpart[tid >> 7][tid & 127] = (c0 + c1) + (c2 + c3);
    }
    __syncthreads();
    if (tid < 128) g_ctx[b * EH + d0 + tid] = cpart[0][tid] + cpart[1][tid];
}

// ---------------------------------------------------------------------------
// K3: gate GEMM partials for step t.
//   C[3072][32]: rows <1536 -> W_ih[:,256:] @ ctx ; rows >=1536 -> W_hh @ prev
//   grid = 24 M-tiles x 4 K-chunks = 96 blocks; K-chunk = 128.
//   Weights read ONCE per step.
// ---------------------------------------------------------------------------
constexpr int GM = 128;   // rows per block
constexpr int GKC = 128;  // K per chunk

__global__ void __launch_bounds__(256) k_gates(int t,
                       const float* __restrict__ dec_init,
                       const float* __restrict__ W_ih,
                       const float* __restrict__ W_hh) {
    const int mt = blockIdx.x >> 2;   // 0..23
    const int kc = blockIdx.x & 3;    // 0..3
    const int r0 = mt * GM;           // global row base (0..2944)
    const bool is_ih = (r0 < NG);
    const int tid = threadIdx.x;

    __shared__ __align__(16) float As[32][GM];    // [k][row]
    __shared__ __align__(16) float Bs[32][36];    // [k][b] padded

    // B source vector base (stride 512 per batch)
    const float* bsrc = is_ih
        ? g_ctx
        : ((t == 0) ? dec_init : (g_h + (size_t)(t - 1) * NB * DH));

    const int rp0 = tid >> 3;          // 0..31 -> row pair base
    const int bg = (tid & 7) * 4;      // batch group of 4

    unsigned long long acc[2][4];
#pragma unroll
    for (int p = 0; p < 2; p++)
#pragma unroll
        for (int j = 0; j < 4; j++) acc[p][j] = 0ull;

    // A-load indices: 2 threads per row, 16 k each
    const int ar = tid >> 1;             // 0..127
    const int akq = (tid & 1) * 16;      // 0 or 16
    const int grow = r0 + ar;
    const float* wrow = is_ih ? (W_ih + (size_t)grow * IND + NE)
                              : (W_hh + (size_t)(grow - NG) * DH);
    // B-load indices
    const int bb = tid >> 3;             // 0..31
    const int bk4 = (tid & 7) * 4;       // 0..28

#pragma unroll
    for (int kt = 0; kt < GKC / 32; kt++) {
        const int kg0 = kc * GKC + kt * 32;
        // A tile
#pragma unroll
        for (int q = 0; q < 4; q++) {
            float4 a4 = *reinterpret_cast<const float4*>(wrow + kg0 + akq + q * 4);
            As[akq + q * 4 + 0][ar] = a4.x;
            As[akq + q * 4 + 1][ar] = a4.y;
            As[akq + q * 4 + 2][ar] = a4.z;
            As[akq + q * 4 + 3][ar] = a4.w;
        }
        // B tile
        {
            float4 b4 = *reinterpret_cast<const float4*>(bsrc + bb * 512 + kg0 + bk4);
            Bs[bk4 + 0][bb] = b4.x;
            Bs[bk4 + 1][bb] = b4.y;
            Bs[bk4 + 2][bb] = b4.z;
            Bs[bk4 + 3][bb] = b4.w;
        }
        __syncthreads();
#pragma unroll
        for (int kk = 0; kk < 32; kk++) {
            float2 av0 = *reinterpret_cast<const float2*>(&As[kk][2 * rp0]);
            float2 av1 = *reinterpret_cast<const float2*>(&As[kk][2 * rp0 + 64]);
            unsigned long long a20 = pack2(av0.x, av0.y);
            unsigned long long a21 = pack2(av1.x, av1.y);
            float4 bv = *reinterpret_cast<const float4*>(&Bs[kk][bg]);
            float bj[4] = {bv.x, bv.y, bv.z, bv.w};
#pragma unroll
            for (int j = 0; j < 4; j++) {
                unsigned long long b2 = pack2(bj[j], bj[j]);
                ffma2(acc[0][j], a20, b2);
                ffma2(acc[1][j], a21, b2);
            }
        }
        __syncthreads();
    }

    // write partials: g_gpart[(kc*3072 + row)*32 + b]
#pragma unroll
    for (int p = 0; p < 2; p++) {
        const int r = r0 + 2 * rp0 + p * 64;
#pragma unroll
        for (int j = 0; j < 4; j++) {
            float lo, hi;
            unpack2(acc[p][j], lo, hi);
            g_gpart[((size_t)kc * 2 * NG + r) * NB + bg + j] = lo;
            g_gpart[((size_t)kc * 2 * NG + r + 1) * NB + bg + j] = hi;
        }
    }
}

// ---------------------------------------------------------------------------
// K4: combine -> h_t.  grid = 64 blocks x 256 thr; thread = (i, b).
// ---------------------------------------------------------------------------
__global__ void __launch_bounds__(256) k_gruup(int t,
                       const float* __restrict__ dec_init,
                       const float* __restrict__ b_ih,
                       const float* __restrict__ b_hh) {
    const int tid = threadIdx.x;
    const int b = tid & 31;
    const int i = blockIdx.x * 8 + (tid >> 5);

    float gx[3], gh[3];
#pragma unroll
    for (int g = 0; g < 3; g++) {
        const int R = g * DH + i;
        float s1 = g_gxemb[((size_t)t * NG + R) * NB + b] + b_ih[R];
        float s2 = b_hh[R];
#pragma unroll
        for (int kc = 0; kc < NKC; kc++) {
            s1 += g_gpart[((size_t)kc * 2 * NG + R) * NB + b];
            s2 += g_gpart[((size_t)kc * 2 * NG + NG + R) * NB + b];
        }
        gx[g] = s1;
        gh[g] = s2;
    }
    const float r = fast_sigmoid(gx[0] + gh[0]);
    const float z = fast_sigmoid(gx[1] + gh[1]);
    const float n = fast_tanh(gx[2] + r * gh[2]);
    const float prev = (t == 0) ? dec_init[b * DH + i]
                                : g_h[((size_t)(t - 1) * NB + b) * DH + i];
    g_h[((size_t)t * NB + b) * DH + i] = (1.0f - z) * n + z * prev;
}

// ---------------------------------------------------------------------------
// K5: batched FC:  out[(b,t), n] = h_all[(t,b), :] @ W_fc + b_fc
// ---------------------------------------------------------------------------
__global__ void __launch_bounds__(256) k_fc(const float* __restrict__ Wfc,
                                            const float* __restrict__ bfc,
                                            float* __restrict__ out) {
    __shared__ __align__(16) float As[FBK][FBM];
    __shared__ __align__(16) float Bs[FBK][FBN];

    const int n0 = blockIdx.x * FBN;
    const int m0 = blockIdx.y * FBM;
    const int tid = threadIdx.x;
    const int tx = tid & 15;
    const int ty = tid >> 4;
    const int am = tid >> 1;
    const int ak4 = (tid & 1) * 4;
    const int bk = tid >> 5;
    const int bn = (tid & 31) * 4;

    unsigned long long c2[2][2][2][4];
#pragma unroll
    for (int a = 0; a < 2; a++)
#pragma unroll
        for (int p = 0; p < 2; p++)
#pragma unroll
            for (int h = 0; h < 2; h++)
#pragma unroll
                for (int j = 0; j < 4; j++) c2[a][p][h][j] = 0ull;

    for (int kt = 0; kt < DH; kt += FBK) {
        float4 a4 = *reinterpret_cast<const float4*>(
            &g_h[(size_t)(m0 + am) * DH + kt + ak4]);
        As[ak4 + 0][am] = a4.x;
        As[ak4 + 1][am] = a4.y;
        As[ak4 + 2][am] = a4.z;
        As[ak4 + 3][am] = a4.w;
#pragma unroll
        for (int q = 0; q < 4; q++) {
            int n = n0 + bn + q;
            Bs[bk][bn + q] = (n < NV) ? Wfc[(size_t)(kt + bk) * NV + n] : 0.f;
        }
        __syncthreads();

#pragma unroll
        for (int kk = 0; kk < FBK; kk++) {
            unsigned long long a2[2][2];
            float4 bv[2];
#pragma unroll
            for (int h = 0; h < 2; h++) {
                float4 av = *reinterpret_cast<const float4*>(&As[kk][h * 64 + ty * 4]);
                a2[h][0] = pack2(av.x, av.y);
                a2[h][1] = pack2(av.z, av.w);
                bv[h] = *reinterpret_cast<const float4*>(&Bs[kk][h * 64 + tx * 4]);
            }
#pragma unroll
            for (int hb = 0; hb < 2; hb++) {
                float bj[4] = {bv[hb].x, bv[hb].y, bv[hb].z, bv[hb].w};
#pragma unroll
                for (int j = 0; j < 4; j++) {
                    unsigned long long b2 = pack2(bj[j], bj[j]);
#pragma unroll
                    for (int ha = 0; ha < 2; ha++)
#pragma unroll
                        for (int ip = 0; ip < 2; ip++)
                            ffma2(c2[ha][ip][hb][j], a2[ha][ip], b2);
                }
            }
        }
        __syncthreads();
    }

#pragma unroll
    for (int ha = 0; ha < 2; ha++)
#pragma unroll
        for (int ip = 0; ip < 2; ip++) {
            const int m = m0 + ha * 64 + ty * 4 + ip * 2;
#pragma unroll
            for (int hb = 0; hb < 2; hb++)
#pragma unroll
                for (int j = 0; j < 4; j++) {
                    const int n = n0 + hb * 64 + tx * 4 + j;
                    if (n < NV) {
                        float lo, hi;
                        unpack2(c2[ha][ip][hb][j], lo, hi);
                        const float bias = bfc[n];
                        const int t1 = m >> 5, b1 = m & 31;
                        const int t2 = (m + 1) >> 5, b2i = (m + 1) & 31;
                        out[((size_t)(b1 * NT + t1)) * NV + n] = lo + bias;
                        out[((size_t)(b2i * NT + t2)) * NV + n] = hi + bias;
                    }
                }
        }
}

// ---------------------------------------------------------------------------
// Launch
// ---------------------------------------------------------------------------
extern "C" void kernel_launch(void* const* d_in, const int* in_sizes, int n_in,
                              void* d_out, int out_size) {
    const int* y = (const int*)d_in[0];
    const float* enc = (const float*)d_in[1];
    const float* dec_init = (const float*)d_in[2];
    const int* mask = (const int*)d_in[3];
    const float* emb = (const float*)d_in[4];
    const float* W_enc = (const float*)d_in[5];
    const float* W_dec = (const float*)d_in[6];
    const float* v = (const float*)d_in[7];
    const float* W_ih = (const float*)d_in[8];
    const float* W_hh = (const float*)d_in[9];
    const float* b_ih = (const float*)d_in[10];
    const float* b_hh = (const float*)d_in[11];
    const float* W_fc = (const float*)d_in[12];
    const float* b_fc = (const float*)d_in[13];

    float* out = (float*)d_out;
    float* attn_out = out + (size_t)NB * NT * NV;

    k_trih<<<dim3(NG / 32, NE / 32), 256>>>(W_ih);
    k_encproj<<<NB * NS, 256>>>(enc, W_enc);
    k_gxemb<<<dim3(NG / FBN, (NB * NT) / FBM), 256>>>(y, emb);
    for (int t = 0; t < NT; t++) {
        k_energy<<<NB * 4, 256>>>(t, dec_init, W_dec, v);
        k_ctx<<<NB * 4, 256>>>(t, enc, mask, attn_out);
        k_gates<<<96, 256>>>(t, dec_init, W_ih, W_hh);
        k_gruup<<<64, 256>>>(t, dec_init, b_ih, b_hh);
    }
    dim3 gfc((NV + FBN - 1) / FBN, (NB * NT) / FBM);
    k_fc<<<gfc, 256>>>(W_fc, b_fc, out);
}